// round 15
// baseline (speedup 1.0000x reference)
#include <cuda_runtime.h>
#include <cuda_bf16.h>
#include <cuda_fp16.h>
#include <cuda_fp8.h>
#include <cstdint>
#include <math.h>

// ---------------- problem constants ----------------
constexpr int Bq   = 64;
constexpr int NS   = 50;
constexpr int LS   = 60;
constexpr int LQ   = 32;
constexpr int D    = 300;
constexpr int DP   = 320;
constexpr int F    = 256;
constexpr int FS   = 3;
constexpr int Vv   = 100000;
constexpr int QROWS = Bq * LQ;        // 2048
constexpr int SROWS = Bq * NS * LS;   // 192000
constexpr int LT    = NS * LS;        // 3000

constexpr int STK  = 64;            // K fp8 per conv stage
constexpr int STPT = DP / STK;      // 5 stages per tap
constexpr int NSTG = FS * STPT;     // 15 stages

constexpr int STILES = SROWS / 128; // 1500 sentence row-tiles
constexpr int QTILES = QROWS / 128; // 16 question row-tiles

// conv dynamic smem: A 3x8KB @0, B 3x16KB @24576
constexpr int CONV_BOFF = 24576;
constexpr int SMEM_CONV = 73728;

// simpool dynamic-smem layout (byte offsets)
constexpr int OQI   = 0;        // Q ins tile: 32 x 328 bf16 = 20992
constexpr int OQC   = 20992;    // Q conv tile: 32 x 264 bf16 -> 37888
constexpr int OSS   = 38912;    // S pipe: 3 x 8KB -> 63488
constexpr int OSB   = 63488;    // simbuf: 128 x 32 fp32 -> 79872
constexpr int OMISC = 79872;
constexpr int SMEM_SP = 81152;

// ---------------- device scratch ----------------
__device__ __nv_bfloat16 g_qe_bf[(QROWS + 2) * DP];
__device__ __nv_bfloat16 g_se_bf[(SROWS + 2) * DP];
__device__ uint8_t g_qe_f8[(QROWS + 2) * DP];
__device__ uint8_t g_se_f8[(SROWS + 2) * DP];
__device__ uint8_t g_filt_f8[F * FS * DP];
__device__ float g_qn[QROWS];
__device__ float g_sn[SROWS];
__device__ __nv_bfloat16 g_qc_bf[QROWS * F];
__device__ __nv_bfloat16 g_sc_bf[SROWS * F];
__device__ float g_qcn2[QROWS];
__device__ float g_scn2[SROWS];
__device__ float g_sentrel[Bq * NS];

// ---------------- asm helpers ----------------
__device__ __forceinline__ void mma_bf16(float* c,
                                         uint32_t a0, uint32_t a1, uint32_t a2, uint32_t a3,
                                         uint32_t b0, uint32_t b1) {
    asm volatile("mma.sync.aligned.m16n8k16.row.col.f32.bf16.bf16.f32 "
                 "{%0,%1,%2,%3},{%4,%5,%6,%7},{%8,%9},{%0,%1,%2,%3};"
                 : "+f"(c[0]), "+f"(c[1]), "+f"(c[2]), "+f"(c[3])
                 : "r"(a0), "r"(a1), "r"(a2), "r"(a3), "r"(b0), "r"(b1));
}
// fp8 MMA with f16 accumulators (2 packed regs)
__device__ __forceinline__ void mma_fp8h(uint32_t& c0, uint32_t& c1,
                                         uint32_t a0, uint32_t a1, uint32_t a2, uint32_t a3,
                                         uint32_t b0, uint32_t b1) {
    asm volatile("mma.sync.aligned.m16n8k32.row.col.f16.e4m3.e4m3.f16 "
                 "{%0,%1},{%2,%3,%4,%5},{%6,%7},{%0,%1};"
                 : "+r"(c0), "+r"(c1)
                 : "r"(a0), "r"(a1), "r"(a2), "r"(a3), "r"(b0), "r"(b1));
}
__device__ __forceinline__ void ldsm4(uint32_t& r0, uint32_t& r1, uint32_t& r2, uint32_t& r3,
                                      uint32_t addr) {
    asm volatile("ldmatrix.sync.aligned.m8n8.x4.shared.b16 {%0,%1,%2,%3}, [%4];"
                 : "=r"(r0), "=r"(r1), "=r"(r2), "=r"(r3) : "r"(addr));
}
__device__ __forceinline__ void cp_async16(uint32_t dst, const void* src, uint32_t srcsz) {
    asm volatile("cp.async.ca.shared.global [%0], [%1], 16, %2;"
                 :: "r"(dst), "l"(src), "r"(srcsz));
}
__device__ __forceinline__ void cp_commit() { asm volatile("cp.async.commit_group;" ::: "memory"); }
__device__ __forceinline__ void cp_wait0()  { asm volatile("cp.async.wait_group 0;" ::: "memory"); }
__device__ __forceinline__ void cp_wait1()  { asm volatile("cp.async.wait_group 1;" ::: "memory"); }

// ---------------- unified gather -> bf16 + fp8 + norm; also zeroes cn2 ----------------
__global__ void gather_norm_kernel(const float* __restrict__ embeds,
                                   const int* __restrict__ question,
                                   const int* __restrict__ sentences) {
    int warp = (blockIdx.x * blockDim.x + threadIdx.x) >> 5;
    int lane = threadIdx.x & 31;
    if (warp >= QROWS + SROWS) return;
    bool isq = warp < QROWS;
    int r = isq ? warp : warp - QROWS;
    int tok = isq ? question[r] : sentences[r];
    __nv_bfloat16* brow = (isq ? g_qe_bf : g_se_bf) + (size_t)r * DP;
    uint8_t*       frow = (isq ? g_qe_f8 : g_se_f8) + (size_t)r * DP;
    float*         nrm  = (isq ? g_qn    : g_sn);
    float*         cn2  = (isq ? g_qcn2  : g_scn2);
    const float* src = embeds + (size_t)tok * D;

    float ss = 0.0f;
    #pragma unroll
    for (int it = 0; it < 3; ++it) {
        int i = lane * 4 + it * 128;
        if (i < D) {
            float4 v = *(const float4*)&src[i];
            __nv_bfloat16 b0 = __float2bfloat16(v.x);
            __nv_bfloat16 b1 = __float2bfloat16(v.y);
            __nv_bfloat16 b2 = __float2bfloat16(v.z);
            __nv_bfloat16 b3 = __float2bfloat16(v.w);
            __nv_bfloat162 p01 = __halves2bfloat162(b0, b1);
            __nv_bfloat162 p23 = __halves2bfloat162(b2, b3);
            uint2 pk; pk.x = *(uint32_t*)&p01; pk.y = *(uint32_t*)&p23;
            *(uint2*)&brow[i] = pk;
            __nv_fp8_e4m3 f0(v.x), f1(v.y), f2(v.z), f3(v.w);
            uchar4 fc;
            fc.x = *(uint8_t*)&f0; fc.y = *(uint8_t*)&f1;
            fc.z = *(uint8_t*)&f2; fc.w = *(uint8_t*)&f3;
            *(uchar4*)&frow[i] = fc;
            float x0 = __bfloat162float(b0), x1 = __bfloat162float(b1);
            float x2 = __bfloat162float(b2), x3 = __bfloat162float(b3);
            ss += x0 * x0 + x1 * x1 + x2 * x2 + x3 * x3;
        }
    }
    #pragma unroll
    for (int o = 16; o; o >>= 1) ss += __shfl_xor_sync(0xffffffffu, ss, o);
    if (lane == 0) { nrm[r] = sqrtf(ss); cn2[r] = 0.0f; }
}

// ---------------- filter fp32 -> e4m3 ----------------
__global__ void filt_convert_kernel(const float* __restrict__ filt) {
    int idx = blockIdx.x * blockDim.x + threadIdx.x;
    if (idx >= F * FS * D) return;
    int f = idx / (FS * D);
    int r = idx % (FS * D);
    int t = r / D;
    int k = r % D;
    __nv_fp8_e4m3 f8(filt[idx]);
    g_filt_f8[((size_t)f * FS + t) * DP + k] = *(uint8_t*)&f8;
}

// ============================================================================
// conv as GEMM: CTA tile 128(M) x 256(N=all filters), 8 warps 2Mx4N,
// warp tile 64x64. e4m3 MMA m16n8k32 with f16 accumulators. 3-deep cp.async
// pipeline, 2 CTAs/SM. Epilogue: bf16 store + per-row sumsq atomics.
// ============================================================================
__global__ void __launch_bounds__(256, 2) conv_mma_kernel() {
    const int bx  = blockIdx.x;
    const bool isq = (bx >= STILES);
    const uint8_t* X   = isq ? g_qe_f8 : g_se_f8;
    __nv_bfloat16* out = isq ? g_qc_bf : g_sc_bf;
    float* cn2         = isq ? g_qcn2  : g_scn2;
    const int seg      = isq ? LQ : LS;
    const int rbase    = (isq ? (bx - STILES) : bx) * 128;

    extern __shared__ __align__(16) uint8_t sm[];   // A: 3x8KB @0, B: 3x16KB @24576
    uint32_t sb = (uint32_t)__cvta_generic_to_shared(sm);

    const int tid  = threadIdx.x;
    const int lane = tid & 31;
    const int wid  = tid >> 5;
    const int wm   = (wid & 1) * 64;     // 2 warps in M
    const int wn   = (wid >> 1) * 64;    // 4 warps in N
    const int m    = lane >> 3;
    const int rr   = lane & 7;

    // loader roles: A row = tid>>1 (two 16B slots), B row = tid (four 16B slots)
    const int arow  = tid >> 1;
    const int hbase = (tid & 1) * 2;
    const int gr    = rbase + arow;
    const int lpos  = gr % seg;
    const int aswz  = (arow >> 1) & 3;
    const int bswz  = (tid >> 1) & 3;

    // hoisted ldsm offsets (c=0); c=1 address = c0 ^ 32 (slot bit1 = addr bit5)
    uint32_t aoff[4], boff[4];
    #pragma unroll
    for (int i = 0; i < 4; ++i) {
        int rowA = wm + i * 16 + (m & 1) * 8 + rr;
        int phys = (m >> 1) ^ ((rowA >> 1) & 3);
        aoff[i] = (uint32_t)(rowA * 64 + phys * 16);
    }
    #pragma unroll
    for (int jp = 0; jp < 4; ++jp) {
        int rowB = wn + (jp * 2 + (m >> 1)) * 8 + rr;
        int phys = (m & 1) ^ ((rowB >> 1) & 3);
        boff[jp] = (uint32_t)(rowB * 64 + phys * 16);
    }

    uint32_t acc[4][8][2];
    #pragma unroll
    for (int i = 0; i < 4; ++i)
        #pragma unroll
        for (int j = 0; j < 8; ++j) { acc[i][j][0] = 0u; acc[i][j][1] = 0u; }

    auto issue = [&](int s, int buf) {
        int tap = s / STPT;
        int kc  = (s % STPT) * STK;
        uint32_t asz = ((lpos + tap) < seg) ? 16u : 0u;
        const uint8_t* ap = X + (size_t)(gr + tap) * DP + kc;
        uint32_t da = sb + buf * 8192 + arow * 64;
        #pragma unroll
        for (int e = 0; e < 2; ++e) {
            int h = hbase + e;
            cp_async16(da + ((h ^ aswz) << 4), ap + h * 16, asz);
        }
        const uint8_t* bp = g_filt_f8 + ((size_t)tid * FS + tap) * DP + kc;
        uint32_t db = sb + CONV_BOFF + buf * 16384 + tid * 64;
        #pragma unroll
        for (int h = 0; h < 4; ++h)
            cp_async16(db + ((h ^ bswz) << 4), bp + h * 16, 16u);
    };

    issue(0, 0); cp_commit();
    issue(1, 1); cp_commit();

    for (int s = 0; s < NSTG; ++s) {
        if (s + 1 < NSTG) cp_wait1(); else cp_wait0();
        __syncthreads();
        if (s + 2 < NSTG) { issue(s + 2, (s + 2) % 3); cp_commit(); }
        uint32_t abase = sb + (s % 3) * 8192;
        uint32_t bbase = sb + CONV_BOFF + (s % 3) * 16384;

        #pragma unroll
        for (int c = 0; c < 2; ++c) {
            uint32_t cx = (uint32_t)(c << 5);
            uint32_t a[4][4];
            #pragma unroll
            for (int i = 0; i < 4; ++i)
                ldsm4(a[i][0], a[i][1], a[i][2], a[i][3], (abase + aoff[i]) ^ cx);
            uint32_t bbv[8][2];
            #pragma unroll
            for (int jp = 0; jp < 4; ++jp)
                ldsm4(bbv[2 * jp][0], bbv[2 * jp][1], bbv[2 * jp + 1][0], bbv[2 * jp + 1][1],
                      (bbase + boff[jp]) ^ cx);
            #pragma unroll
            for (int j = 0; j < 8; ++j)
                #pragma unroll
                for (int i = 0; i < 4; ++i)
                    mma_fp8h(acc[i][j][0], acc[i][j][1],
                             a[i][0], a[i][1], a[i][2], a[i][3], bbv[j][0], bbv[j][1]);
        }
        __syncthreads();
    }

    // ---- epilogue: f16 accs -> bf16 store + per-row sumsq ----
    const int g   = lane >> 2;
    const int tig = lane & 3;
    #pragma unroll
    for (int i = 0; i < 4; ++i) {
        int r0 = rbase + wm + i * 16 + g;
        float sq0 = 0.0f, sq8 = 0.0f;
        #pragma unroll
        for (int j = 0; j < 8; ++j) {
            int col = wn + j * 8 + tig * 2;
            float2 f01 = __half22float2(*(__half2*)&acc[i][j][0]);  // row g
            float2 f23 = __half22float2(*(__half2*)&acc[i][j][1]);  // row g+8
            __nv_bfloat16 h0 = __float2bfloat16(f01.x);
            __nv_bfloat16 h1 = __float2bfloat16(f01.y);
            __nv_bfloat16 h2 = __float2bfloat16(f23.x);
            __nv_bfloat16 h3 = __float2bfloat16(f23.y);
            __nv_bfloat16* o0 = out + (size_t)r0 * F + col;
            *(__nv_bfloat162*)o0 = __halves2bfloat162(h0, h1);
            *(__nv_bfloat162*)(o0 + (size_t)8 * F) = __halves2bfloat162(h2, h3);
            float f0 = __bfloat162float(h0), f1 = __bfloat162float(h1);
            float f2 = __bfloat162float(h2), f3 = __bfloat162float(h3);
            sq0 += f0 * f0 + f1 * f1;
            sq8 += f2 * f2 + f3 * f3;
        }
        sq0 += __shfl_xor_sync(0xffffffffu, sq0, 1);
        sq0 += __shfl_xor_sync(0xffffffffu, sq0, 2);
        sq8 += __shfl_xor_sync(0xffffffffu, sq8, 1);
        sq8 += __shfl_xor_sync(0xffffffffu, sq8, 2);
        if (tig == 0) {
            atomicAdd(&cn2[r0], sq0);
            atomicAdd(&cn2[r0 + 8], sq8);
        }
    }
}

// ============================================================================
// fused sim + pool (unchanged from R14 passing version)
// ============================================================================
__device__ __forceinline__ void insert5(float* t, float v) {
    if (v > t[4]) {
        t[4] = v;
        #pragma unroll
        for (int i = 4; i > 0; --i) {
            if (t[i] > t[i - 1]) { float tmp = t[i - 1]; t[i - 1] = t[i]; t[i] = tmp; }
        }
    }
}

template<int KT, int STRIDE, bool SQN>
__device__ __forceinline__ void sim_phase(
    uint32_t sbS, uint32_t sbQ,
    const __nv_bfloat16* __restrict__ S0,
    const __nv_bfloat16* __restrict__ S1,
    float* __restrict__ simbuf,
    const float* __restrict__ qns,
    const float* __restrict__ sn0,
    const float* __restrict__ sn1,
    int tid)
{
    constexpr int STG = KT / 32;
    constexpr int QS  = KT + 8;

    const int lane = tid & 31;
    const int wid  = tid >> 5;
    const int m    = lane >> 3;
    const int rr   = lane & 7;

    const int srow  = tid >> 1;
    const int hbase = (tid & 1) * 2;
    const int sl    = srow & 63;
    const int ssent = srow >> 6;
    const int swz   = (srow >> 1) & 3;
    const uint32_t ssz = (sl < LS) ? 16u : 0u;
    const __nv_bfloat16* srcrow = (ssent ? S1 : S0) + (size_t)sl * STRIDE;

    auto issueS = [&](int s, int buf) {
        int kc = s * 32;
        #pragma unroll
        for (int e = 0; e < 2; ++e) {
            int h = hbase + e;
            int phys = h ^ swz;
            cp_async16(sbS + buf * 8192 + srow * 64 + phys * 16, srcrow + kc + h * 8, ssz);
        }
    };

    float acc[4][4];
    #pragma unroll
    for (int t = 0; t < 4; ++t)
        #pragma unroll
        for (int v = 0; v < 4; ++v) acc[t][v] = 0.0f;

    issueS(0, 0); cp_commit();
    issueS(1, 1); cp_commit();

    for (int s = 0; s < STG; ++s) {
        if (s + 1 < STG) cp_wait1(); else cp_wait0();
        __syncthreads();
        if (s + 2 < STG) { issueS(s + 2, (s + 2) % 3); cp_commit(); }
        uint32_t abase = sbS + (s % 3) * 8192;

        #pragma unroll
        for (int c = 0; c < 2; ++c) {
            uint32_t a[4];
            int rowS = wid * 16 + (m & 1) * 8 + rr;
            int phys = (2 * c + (m >> 1)) ^ ((rowS >> 1) & 3);
            ldsm4(a[0], a[1], a[2], a[3], abase + (uint32_t)(rowS * 64 + phys * 16));

            int cg = s * 2 + c;
            uint32_t qb[4][2];
            #pragma unroll
            for (int jp = 0; jp < 2; ++jp) {
                int rowq = (jp * 2 + (m >> 1)) * 8 + rr;
                uint32_t qaddr = sbQ + (uint32_t)(rowq * (QS * 2) + (cg * 16 + (m & 1) * 8) * 2);
                ldsm4(qb[2 * jp][0], qb[2 * jp][1], qb[2 * jp + 1][0], qb[2 * jp + 1][1], qaddr);
            }
            #pragma unroll
            for (int t = 0; t < 4; ++t)
                mma_bf16(acc[t], a[0], a[1], a[2], a[3], qb[t][0], qb[t][1]);
        }
        __syncthreads();
    }

    const int g   = lane >> 2;
    const int tig = lane & 3;
    int l0 = wid * 16 + g;
    int l1 = l0 + 8;
    int li0 = l0 & 63, li1 = l1 & 63;
    float r0 = (li0 < LS) ? ((l0 >> 6) ? sn1[li0] : sn0[li0]) : 1.0f;
    float r1 = (li1 < LS) ? ((l1 >> 6) ? sn1[li1] : sn0[li1]) : 1.0f;
    float n0 = SQN ? sqrtf(r0) : r0;
    float n1 = SQN ? sqrtf(r1) : r1;
    #pragma unroll
    for (int t = 0; t < 4; ++t) {
        int q0 = t * 8 + tig * 2;
        float i0 = 1.0f / (qns[q0] * n0), i1 = 1.0f / (qns[q0 + 1] * n0);
        float i2 = 1.0f / (qns[q0] * n1), i3 = 1.0f / (qns[q0 + 1] * n1);
        if (li0 < LS) {
            simbuf[l0 * 32 + q0]     = acc[t][0] * i0;
            simbuf[l0 * 32 + q0 + 1] = acc[t][1] * i1;
        }
        if (li1 < LS) {
            simbuf[l1 * 32 + q0]     = acc[t][2] * i2;
            simbuf[l1 * 32 + q0 + 1] = acc[t][3] * i3;
        }
    }
}

__global__ void __launch_bounds__(256, 2) simpool_kernel(
    const int* __restrict__ question,
    const int* __restrict__ sentences,
    const float* __restrict__ Wg,
    const float* __restrict__ biasg,
    float* __restrict__ out_sent)
{
    extern __shared__ __align__(16) uint8_t dyn[];
    __nv_bfloat16* Qi = (__nv_bfloat16*)(dyn + OQI);
    __nv_bfloat16* Qc = (__nv_bfloat16*)(dyn + OQC);
    float* simbuf = (float*)(dyn + OSB);
    float* qns  = (float*)(dyn + OMISC);
    float* qcns = (float*)(dyn + OMISC + 128);
    float* zbuf = (float*)(dyn + OMISC + 256);
    int*   smk  = (int*)(dyn + OMISC + 512);
    int*   qmk  = (int*)(dyn + OMISC + 1024);
    float* Wc   = (float*)(dyn + OMISC + 1152);
    uint32_t sbS  = (uint32_t)__cvta_generic_to_shared(dyn + OSS);
    uint32_t sbQi = (uint32_t)__cvta_generic_to_shared(Qi);
    uint32_t sbQc = (uint32_t)__cvta_generic_to_shared(Qc);

    const int tid = threadIdx.x;
    const int b   = blockIdx.y;
    const int n0  = blockIdx.x * 2;

    constexpr int QSI = DP + 8, QSC = F + 8;
    const __nv_bfloat16* Qig = g_qe_bf + (size_t)b * LQ * DP;
    const __nv_bfloat16* Qcg = g_qc_bf + (size_t)b * LQ * F;
    for (int idx = tid; idx < 32 * (DP / 8); idx += 256) {
        int row = idx / (DP / 8), s8 = idx % (DP / 8);
        *(uint4*)&Qi[row * QSI + s8 * 8] = *(const uint4*)&Qig[(size_t)row * DP + s8 * 8];
    }
    for (int idx = tid; idx < 32 * (F / 8); idx += 256) {
        int row = idx / (F / 8), s8 = idx % (F / 8);
        *(uint4*)&Qc[row * QSC + s8 * 8] = *(const uint4*)&Qcg[(size_t)row * F + s8 * 8];
    }
    if (tid < 32) {
        qns[tid]  = g_qn[b * LQ + tid];
        qcns[tid] = sqrtf(g_qcn2[b * LQ + tid]);
        qmk[tid]  = question[b * LQ + tid] > 0;
    }
    for (int idx = tid; idx < 128; idx += 256) {
        int sent = idx >> 6, l = idx & 63;
        smk[idx] = (l < LS) ? (sentences[((size_t)b * NS + n0 + sent) * LS + l] > 0) : 0;
    }
    if (tid < 7) Wc[tid] = (tid < 6) ? Wg[tid] : biasg[0];
    __syncthreads();

    const float* sn0i = g_sn   + (size_t)b * LT + (size_t)n0 * LS;
    const float* sn1i = sn0i + LS;
    const float* sn0c = g_scn2 + (size_t)b * LT + (size_t)n0 * LS;
    const float* sn1c = sn0c + LS;
    const __nv_bfloat16* S0i = g_se_bf + ((size_t)b * LT + (size_t)n0 * LS) * DP;
    const __nv_bfloat16* S0c = g_sc_bf + ((size_t)b * LT + (size_t)n0 * LS) * F;

    const float thr = (float)(1.0 - 1e-5);

    const int grp = tid >> 2;
    const int sub = tid & 3;
    const int psent = grp >> 5, pq = grp & 31;

    // ---- phase A: sim_ins ----
    sim_phase<DP, DP, false>(sbS, sbQi, S0i, S0i + (size_t)LS * DP, simbuf, qns, sn0i, sn1i, tid);
    __syncthreads();
    {
        bool qm = qmk[pq] != 0;
        const float* col = simbuf + psent * 64 * 32 + pq;
        const int* sm = smk + psent * 64;
        float ti[5] = {-INFINITY, -INFINITY, -INFINITY, -INFINITY, -INFINITY};
        int cnt = 0;
        int lb = sub * 15;
        for (int l = lb; l < lb + 15; ++l) {
            float v = col[l * 32];
            if (v >= thr) ++cnt;
            float mv = (qm && sm[l]) ? v : 0.0f;
            insert5(ti, mv);
        }
        #pragma unroll
        for (int off = 1; off <= 2; off <<= 1) {
            cnt += __shfl_xor_sync(0xffffffffu, cnt, off);
            float ov[5];
            #pragma unroll
            for (int k = 0; k < 5; ++k) ov[k] = __shfl_xor_sync(0xffffffffu, ti[k], off);
            #pragma unroll
            for (int k = 0; k < 5; ++k) insert5(ti, ov[k]);
        }
        if (sub == 0) {
            float insMean = (ti[0] + ti[1] + ti[2] + ti[3] + ti[4]) * 0.2f;
            float ohMax   = (cnt > 0) ? 1.0f : 0.0f;
            float ohMean  = fminf((float)cnt, 5.0f) * 0.2f;
            zbuf[grp] = Wc[0] * ti[0] + Wc[1] * insMean + Wc[4] * ohMax + Wc[5] * ohMean;
        }
    }
    __syncthreads();

    // ---- phase B: sim_sen ----
    sim_phase<F, F, true>(sbS, sbQc, S0c, S0c + (size_t)LS * F, simbuf, qcns, sn0c, sn1c, tid);
    __syncthreads();
    {
        bool qm = qmk[pq] != 0;
        const float* col = simbuf + psent * 64 * 32 + pq;
        const int* sm = smk + psent * 64;
        float tc[5] = {-INFINITY, -INFINITY, -INFINITY, -INFINITY, -INFINITY};
        int lb = sub * 15;
        for (int l = lb; l < lb + 15; ++l) {
            float v = col[l * 32];
            float mv = (qm && sm[l]) ? v : 0.0f;
            insert5(tc, mv);
        }
        #pragma unroll
        for (int off = 1; off <= 2; off <<= 1) {
            float ov[5];
            #pragma unroll
            for (int k = 0; k < 5; ++k) ov[k] = __shfl_xor_sync(0xffffffffu, tc[k], off);
            #pragma unroll
            for (int k = 0; k < 5; ++k) insert5(tc, ov[k]);
        }
        if (sub == 0) {
            float senMean = (tc[0] + tc[1] + tc[2] + tc[3] + tc[4]) * 0.2f;
            float z = zbuf[grp] + Wc[2] * tc[0] + Wc[3] * senMean + Wc[6];
            zbuf[grp] = 1.0f / (1.0f + expf(-z));
        }
    }
    __syncthreads();
    if (tid < 2) {
        float s = 0.0f;
        for (int q = 0; q < 32; ++q) s += zbuf[tid * 32 + q];
        float sr = s * (1.0f / (float)LQ);
        int bn = b * NS + n0 + tid;
        g_sentrel[bn] = sr;
        if (out_sent) out_sent[bn] = sr;
    }
}

// ---------------- doc max + BCE losses ----------------
__global__ void final_kernel(const int* __restrict__ tsents,
                             const int* __restrict__ tdocs,
                             float* __restrict__ out_loss,
                             float* __restrict__ out_doc) {
    __shared__ float red[256];
    __shared__ float docs_s[Bq];
    int tid = threadIdx.x;
    const float eps = 1e-7f;
    const float hi  = (float)(1.0 - 1e-7);

    float s1 = 0.0f;
    for (int i = tid; i < Bq * NS; i += 256) {
        float p = fminf(fmaxf(g_sentrel[i], eps), hi);
        float t = (float)tsents[i];
        s1 += t * logf(p) + (1.0f - t) * log1pf(-p);
    }
    red[tid] = s1;
    __syncthreads();
    for (int s = 128; s > 0; s >>= 1) {
        if (tid < s) red[tid] += red[tid + s];
        __syncthreads();
    }
    float bce1 = -red[0] / (float)(Bq * NS);
    __syncthreads();

    if (tid < Bq) {
        float m = -INFINITY;
        for (int n = 0; n < NS; ++n) m = fmaxf(m, g_sentrel[tid * NS + n]);
        docs_s[tid] = m;
        if (out_doc) out_doc[tid] = m;
    }
    __syncthreads();

    float s2 = 0.0f;
    if (tid < Bq) {
        float p = fminf(fmaxf(docs_s[tid], eps), hi);
        float t = (float)tdocs[tid];
        s2 = t * logf(p) + (1.0f - t) * log1pf(-p);
    }
    red[tid] = s2;
    __syncthreads();
    for (int s = 128; s > 0; s >>= 1) {
        if (tid < s) red[tid] += red[tid + s];
        __syncthreads();
    }
    if (tid == 0) {
        float bce2 = -red[0] / (float)Bq;
        out_loss[0] = 0.5f * (bce1 + bce2);
    }
}

// ---------------- host ----------------
extern "C" void kernel_launch(void* const* d_in, const int* in_sizes, int n_in,
                              void* d_out, int out_size) {
    const int *sentences = nullptr, *question = nullptr, *tsents = nullptr, *tdocs = nullptr;
    const float *embeds = nullptr, *filters = nullptr, *W = nullptr, *bias = nullptr;

    for (int i = 0; i < n_in; ++i) {
        switch (in_sizes[i]) {
            case SROWS:        sentences = (const int*)d_in[i];  break;
            case QROWS:        question  = (const int*)d_in[i];  break;
            case Bq * NS:      tsents    = (const int*)d_in[i];  break;
            case Bq:           tdocs     = (const int*)d_in[i];  break;
            case Vv * D:       embeds    = (const float*)d_in[i]; break;
            case F * FS * D:   filters   = (const float*)d_in[i]; break;
            case 6:            W         = (const float*)d_in[i]; break;
            case 1:            bias      = (const float*)d_in[i]; break;
            default: break;
        }
    }

    float* out = (float*)d_out;
    float* out_sent = (out_size >= 1 + Bq * NS)      ? out + 1            : nullptr;
    float* out_doc  = (out_size >= 1 + Bq * NS + Bq) ? out + 1 + Bq * NS  : nullptr;

    cudaFuncSetAttribute(conv_mma_kernel, cudaFuncAttributeMaxDynamicSharedMemorySize, SMEM_CONV);
    cudaFuncSetAttribute(simpool_kernel, cudaFuncAttributeMaxDynamicSharedMemorySize, SMEM_SP);

    // 1: filters -> e4m3
    filt_convert_kernel<<<(F * FS * D + 255) / 256, 256>>>(filters);

    // 2: unified gather (question + sentences) + norms + cn2 zeroing
    gather_norm_kernel<<<((QROWS + SROWS) * 32 + 255) / 256, 256>>>(embeds, question, sentences);

    // 3: conv (128x256 CTA tile, f16-accum fp8 MMA, 3-deep pipeline) + row sumsq
    conv_mma_kernel<<<STILES + QTILES, 256, SMEM_CONV>>>();

    // 4: fused sim + pool
    simpool_kernel<<<dim3(NS / 2, Bq), 256, SMEM_SP>>>(question, sentences, W, bias, out_sent);

    // 5: doc max + BCE
    final_kernel<<<1, 256>>>(tsents, tdocs, out, out_doc);
}

// round 16
// speedup vs baseline: 1.0562x; 1.0562x over previous
#include <cuda_runtime.h>
#include <cuda_bf16.h>
#include <cuda_fp8.h>
#include <cstdint>
#include <math.h>

// ---------------- problem constants ----------------
constexpr int Bq   = 64;
constexpr int NS   = 50;
constexpr int LS   = 60;
constexpr int LQ   = 32;
constexpr int D    = 300;
constexpr int DP   = 320;
constexpr int F    = 256;
constexpr int FS   = 3;
constexpr int Vv   = 100000;
constexpr int QROWS = Bq * LQ;        // 2048
constexpr int SROWS = Bq * NS * LS;   // 192000
constexpr int LT    = NS * LS;        // 3000

constexpr int STK  = 64;            // K fp8 per conv stage
constexpr int STPT = DP / STK;      // 5 stages per tap
constexpr int NSTG = FS * STPT;     // 15 stages

constexpr int STILES = SROWS / 128; // 1500 sentence row-tiles
constexpr int QTILES = QROWS / 128; // 16 question row-tiles

// conv dynamic smem: A 3x8KB @0, B 3x8KB @24576
constexpr int SMEM_CONV = 49152;

// simpool dynamic-smem layout (byte offsets) — 2-deep S pipe, <76.8KB for 3 CTAs/SM
constexpr int OQI   = 0;        // Q ins tile: 32 x 328 bf16 = 20992
constexpr int OQC   = 20992;    // Q conv tile: 32 x 264 bf16 -> 37888
constexpr int OSS   = 38912;    // S pipe: 2 x 8KB -> 55296
constexpr int OSB   = 55296;    // simbuf: 128 x 32 fp32 -> 71680
constexpr int OMISC = 71680;    // qns(128) qcns(128) zbuf(256) smk(512) qmk(128) W(32)
constexpr int SMEM_SP = 72960;

// ---------------- device scratch ----------------
__device__ __nv_bfloat16 g_qe_bf[(QROWS + 2) * DP];
__device__ __nv_bfloat16 g_se_bf[(SROWS + 2) * DP];
__device__ uint8_t g_qe_f8[(QROWS + 2) * DP];
__device__ uint8_t g_se_f8[(SROWS + 2) * DP];
__device__ uint8_t g_filt_f8[F * FS * DP];
__device__ float g_qn[QROWS];
__device__ float g_sn[SROWS];
__device__ __nv_bfloat16 g_qc_bf[QROWS * F];
__device__ __nv_bfloat16 g_sc_bf[SROWS * F];
__device__ float g_qcn2[QROWS];
__device__ float g_scn2[SROWS];
__device__ float g_sentrel[Bq * NS];

// ---------------- asm helpers ----------------
__device__ __forceinline__ void mma_bf16(float* c,
                                         uint32_t a0, uint32_t a1, uint32_t a2, uint32_t a3,
                                         uint32_t b0, uint32_t b1) {
    asm volatile("mma.sync.aligned.m16n8k16.row.col.f32.bf16.bf16.f32 "
                 "{%0,%1,%2,%3},{%4,%5,%6,%7},{%8,%9},{%0,%1,%2,%3};"
                 : "+f"(c[0]), "+f"(c[1]), "+f"(c[2]), "+f"(c[3])
                 : "r"(a0), "r"(a1), "r"(a2), "r"(a3), "r"(b0), "r"(b1));
}
__device__ __forceinline__ void mma_fp8(float* c,
                                        uint32_t a0, uint32_t a1, uint32_t a2, uint32_t a3,
                                        uint32_t b0, uint32_t b1) {
    asm volatile("mma.sync.aligned.m16n8k32.row.col.f32.e4m3.e4m3.f32 "
                 "{%0,%1,%2,%3},{%4,%5,%6,%7},{%8,%9},{%0,%1,%2,%3};"
                 : "+f"(c[0]), "+f"(c[1]), "+f"(c[2]), "+f"(c[3])
                 : "r"(a0), "r"(a1), "r"(a2), "r"(a3), "r"(b0), "r"(b1));
}
__device__ __forceinline__ void ldsm4(uint32_t& r0, uint32_t& r1, uint32_t& r2, uint32_t& r3,
                                      uint32_t addr) {
    asm volatile("ldmatrix.sync.aligned.m8n8.x4.shared.b16 {%0,%1,%2,%3}, [%4];"
                 : "=r"(r0), "=r"(r1), "=r"(r2), "=r"(r3) : "r"(addr));
}
__device__ __forceinline__ void cp_async16(uint32_t dst, const void* src, uint32_t srcsz) {
    asm volatile("cp.async.ca.shared.global [%0], [%1], 16, %2;"
                 :: "r"(dst), "l"(src), "r"(srcsz));
}
__device__ __forceinline__ void cp_commit() { asm volatile("cp.async.commit_group;" ::: "memory"); }
__device__ __forceinline__ void cp_wait0()  { asm volatile("cp.async.wait_group 0;" ::: "memory"); }
__device__ __forceinline__ void cp_wait1()  { asm volatile("cp.async.wait_group 1;" ::: "memory"); }

// ---------------- unified gather -> bf16 + fp8 + norm; also zeroes cn2 ----------------
__global__ void gather_norm_kernel(const float* __restrict__ embeds,
                                   const int* __restrict__ question,
                                   const int* __restrict__ sentences) {
    int warp = (blockIdx.x * blockDim.x + threadIdx.x) >> 5;
    int lane = threadIdx.x & 31;
    if (warp >= QROWS + SROWS) return;
    bool isq = warp < QROWS;
    int r = isq ? warp : warp - QROWS;
    int tok = isq ? question[r] : sentences[r];
    __nv_bfloat16* brow = (isq ? g_qe_bf : g_se_bf) + (size_t)r * DP;
    uint8_t*       frow = (isq ? g_qe_f8 : g_se_f8) + (size_t)r * DP;
    float*         nrm  = (isq ? g_qn    : g_sn);
    float*         cn2  = (isq ? g_qcn2  : g_scn2);
    const float* src = embeds + (size_t)tok * D;

    float ss = 0.0f;
    #pragma unroll
    for (int it = 0; it < 3; ++it) {
        int i = lane * 4 + it * 128;
        if (i < D) {
            float4 v = *(const float4*)&src[i];
            __nv_bfloat16 b0 = __float2bfloat16(v.x);
            __nv_bfloat16 b1 = __float2bfloat16(v.y);
            __nv_bfloat16 b2 = __float2bfloat16(v.z);
            __nv_bfloat16 b3 = __float2bfloat16(v.w);
            __nv_bfloat162 p01 = __halves2bfloat162(b0, b1);
            __nv_bfloat162 p23 = __halves2bfloat162(b2, b3);
            uint2 pk; pk.x = *(uint32_t*)&p01; pk.y = *(uint32_t*)&p23;
            *(uint2*)&brow[i] = pk;
            __nv_fp8_e4m3 f0(v.x), f1(v.y), f2(v.z), f3(v.w);
            uchar4 fc;
            fc.x = *(uint8_t*)&f0; fc.y = *(uint8_t*)&f1;
            fc.z = *(uint8_t*)&f2; fc.w = *(uint8_t*)&f3;
            *(uchar4*)&frow[i] = fc;
            float x0 = __bfloat162float(b0), x1 = __bfloat162float(b1);
            float x2 = __bfloat162float(b2), x3 = __bfloat162float(b3);
            ss += x0 * x0 + x1 * x1 + x2 * x2 + x3 * x3;
        }
    }
    #pragma unroll
    for (int o = 16; o; o >>= 1) ss += __shfl_xor_sync(0xffffffffu, ss, o);
    if (lane == 0) { nrm[r] = sqrtf(ss); cn2[r] = 0.0f; }
}

// ---------------- filter fp32 -> e4m3 ----------------
__global__ void filt_convert_kernel(const float* __restrict__ filt) {
    int idx = blockIdx.x * blockDim.x + threadIdx.x;
    if (idx >= F * FS * D) return;
    int f = idx / (FS * D);
    int r = idx % (FS * D);
    int t = r / D;
    int k = r % D;
    __nv_fp8_e4m3 f8(filt[idx]);
    g_filt_f8[((size_t)f * FS + t) * DP + k] = *(uint8_t*)&f8;
}

// ============================================================================
// conv (R14 version, verbatim): 128x128 CTA tile, 8 warps 4Mx2N, fp32 acc,
// e4m3 MMA m16n8k32, 3-deep cp.async pipeline, 2 CTAs/SM.
// ============================================================================
__global__ void __launch_bounds__(256, 2) conv_mma_kernel() {
    const int bx  = blockIdx.x;
    const bool isq = (bx >= STILES);
    const uint8_t* X   = isq ? g_qe_f8 : g_se_f8;
    __nv_bfloat16* out = isq ? g_qc_bf : g_sc_bf;
    float* cn2         = isq ? g_qcn2  : g_scn2;
    const int seg      = isq ? LQ : LS;
    const int rbase    = (isq ? (bx - STILES) : bx) * 128;

    extern __shared__ __align__(16) uint8_t sm[];   // A: 3x8KB @0, B: 3x8KB @24576
    uint32_t sb = (uint32_t)__cvta_generic_to_shared(sm);

    const int tid  = threadIdx.x;
    const int lane = tid & 31;
    const int wid  = tid >> 5;
    const int wm   = (wid & 3) * 32;
    const int wn   = (wid >> 2) * 64;
    const int m    = lane >> 3;
    const int rr   = lane & 7;

    const int fbase = blockIdx.y * 128;

    const int arow  = tid >> 1;
    const int hbase = (tid & 1) * 2;
    const int gr    = rbase + arow;
    const int lpos  = gr % seg;
    const int gf    = fbase + arow;
    const int swz   = (arow >> 1) & 3;

    float acc[2][8][4];
    #pragma unroll
    for (int i = 0; i < 2; ++i)
        #pragma unroll
        for (int j = 0; j < 8; ++j)
            #pragma unroll
            for (int v = 0; v < 4; ++v) acc[i][j][v] = 0.0f;

    auto issue = [&](int s, int buf) {
        int tap = s / STPT;
        int kc  = (s % STPT) * STK;
        uint32_t asz = ((lpos + tap) < seg) ? 16u : 0u;
        const uint8_t* ap = X + (size_t)(gr + tap) * DP + kc;
        const uint8_t* bp = g_filt_f8 + ((size_t)gf * FS + tap) * DP + kc;
        #pragma unroll
        for (int e = 0; e < 2; ++e) {
            int h = hbase + e;
            int phys = h ^ swz;
            uint32_t da = sb + buf * 8192 + arow * 64 + phys * 16;
            uint32_t db = da + 24576;
            cp_async16(da, ap + h * 16, asz);
            cp_async16(db, bp + h * 16, 16u);
        }
    };

    issue(0, 0); cp_commit();
    issue(1, 1); cp_commit();

    for (int s = 0; s < NSTG; ++s) {
        if (s + 1 < NSTG) cp_wait1(); else cp_wait0();
        __syncthreads();
        if (s + 2 < NSTG) { issue(s + 2, (s + 2) % 3); cp_commit(); }
        uint32_t abase = sb + (s % 3) * 8192;
        uint32_t bbase = abase + 24576;

        #pragma unroll
        for (int c = 0; c < 2; ++c) {
            uint32_t a[2][4];
            #pragma unroll
            for (int i = 0; i < 2; ++i) {
                int rowA = wm + i * 16 + (m & 1) * 8 + rr;
                int phys = (2 * c + (m >> 1)) ^ ((rowA >> 1) & 3);
                ldsm4(a[i][0], a[i][1], a[i][2], a[i][3],
                      abase + (uint32_t)(rowA * 64 + phys * 16));
            }
            uint32_t bbv[8][2];
            #pragma unroll
            for (int jp = 0; jp < 4; ++jp) {
                int rowB = wn + (jp * 2 + (m >> 1)) * 8 + rr;
                int phys = (2 * c + (m & 1)) ^ ((rowB >> 1) & 3);
                ldsm4(bbv[2 * jp][0], bbv[2 * jp][1], bbv[2 * jp + 1][0], bbv[2 * jp + 1][1],
                      bbase + (uint32_t)(rowB * 64 + phys * 16));
            }
            #pragma unroll
            for (int j = 0; j < 8; ++j)
                #pragma unroll
                for (int i = 0; i < 2; ++i)
                    mma_fp8(acc[i][j], a[i][0], a[i][1], a[i][2], a[i][3],
                            bbv[j][0], bbv[j][1]);
        }
        __syncthreads();
    }

    const int g   = lane >> 2;
    const int tig = lane & 3;
    #pragma unroll
    for (int i = 0; i < 2; ++i) {
        int r0 = rbase + wm + i * 16 + g;
        float sq0 = 0.0f, sq8 = 0.0f;
        #pragma unroll
        for (int j = 0; j < 8; ++j) {
            int col = fbase + wn + j * 8 + tig * 2;
            __nv_bfloat16 h0 = __float2bfloat16(acc[i][j][0]);
            __nv_bfloat16 h1 = __float2bfloat16(acc[i][j][1]);
            __nv_bfloat16 h2 = __float2bfloat16(acc[i][j][2]);
            __nv_bfloat16 h3 = __float2bfloat16(acc[i][j][3]);
            __nv_bfloat16* o0 = out + (size_t)r0 * F + col;
            *(__nv_bfloat162*)o0 = __halves2bfloat162(h0, h1);
            *(__nv_bfloat162*)(o0 + (size_t)8 * F) = __halves2bfloat162(h2, h3);
            float f0 = __bfloat162float(h0), f1 = __bfloat162float(h1);
            float f2 = __bfloat162float(h2), f3 = __bfloat162float(h3);
            sq0 += f0 * f0 + f1 * f1;
            sq8 += f2 * f2 + f3 * f3;
        }
        sq0 += __shfl_xor_sync(0xffffffffu, sq0, 1);
        sq0 += __shfl_xor_sync(0xffffffffu, sq0, 2);
        sq8 += __shfl_xor_sync(0xffffffffu, sq8, 1);
        sq8 += __shfl_xor_sync(0xffffffffu, sq8, 2);
        if (tig == 0) {
            atomicAdd(&cn2[r0], sq0);
            atomicAdd(&cn2[r0 + 8], sq8);
        }
    }
}

// ============================================================================
// fused sim + pool: 2-deep S pipe + 85-reg cap -> 3 CTAs/SM (was 2)
// ============================================================================
__device__ __forceinline__ void insert5(float* t, float v) {
    if (v > t[4]) {
        t[4] = v;
        #pragma unroll
        for (int i = 4; i > 0; --i) {
            if (t[i] > t[i - 1]) { float tmp = t[i - 1]; t[i - 1] = t[i]; t[i] = tmp; }
        }
    }
}

template<int KT, int STRIDE, bool SQN>
__device__ __forceinline__ void sim_phase(
    uint32_t sbS, uint32_t sbQ,
    const __nv_bfloat16* __restrict__ S0,
    const __nv_bfloat16* __restrict__ S1,
    float* __restrict__ simbuf,
    const float* __restrict__ qns,
    const float* __restrict__ sn0,
    const float* __restrict__ sn1,
    int tid)
{
    constexpr int STG = KT / 32;
    constexpr int QS  = KT + 8;

    const int lane = tid & 31;
    const int wid  = tid >> 5;
    const int m    = lane >> 3;
    const int rr   = lane & 7;

    const int srow  = tid >> 1;
    const int hbase = (tid & 1) * 2;
    const int sl    = srow & 63;
    const int ssent = srow >> 6;
    const int swz   = (srow >> 1) & 3;
    const uint32_t ssz = (sl < LS) ? 16u : 0u;
    const __nv_bfloat16* srcrow = (ssent ? S1 : S0) + (size_t)sl * STRIDE;

    auto issueS = [&](int s, int buf) {
        int kc = s * 32;
        #pragma unroll
        for (int e = 0; e < 2; ++e) {
            int h = hbase + e;
            int phys = h ^ swz;
            cp_async16(sbS + buf * 8192 + srow * 64 + phys * 16, srcrow + kc + h * 8, ssz);
        }
    };

    float acc[4][4];
    #pragma unroll
    for (int t = 0; t < 4; ++t)
        #pragma unroll
        for (int v = 0; v < 4; ++v) acc[t][v] = 0.0f;

    issueS(0, 0); cp_commit();

    for (int s = 0; s < STG; ++s) {
        cp_wait0();
        __syncthreads();
        if (s + 1 < STG) { issueS(s + 1, (s + 1) & 1); cp_commit(); }
        uint32_t abase = sbS + (s & 1) * 8192;

        #pragma unroll
        for (int c = 0; c < 2; ++c) {
            uint32_t a[4];
            int rowS = wid * 16 + (m & 1) * 8 + rr;
            int phys = (2 * c + (m >> 1)) ^ ((rowS >> 1) & 3);
            ldsm4(a[0], a[1], a[2], a[3], abase + (uint32_t)(rowS * 64 + phys * 16));

            int cg = s * 2 + c;
            uint32_t qb[4][2];
            #pragma unroll
            for (int jp = 0; jp < 2; ++jp) {
                int rowq = (jp * 2 + (m >> 1)) * 8 + rr;
                uint32_t qaddr = sbQ + (uint32_t)(rowq * (QS * 2) + (cg * 16 + (m & 1) * 8) * 2);
                ldsm4(qb[2 * jp][0], qb[2 * jp][1], qb[2 * jp + 1][0], qb[2 * jp + 1][1], qaddr);
            }
            #pragma unroll
            for (int t = 0; t < 4; ++t)
                mma_bf16(acc[t], a[0], a[1], a[2], a[3], qb[t][0], qb[t][1]);
        }
        __syncthreads();
    }

    const int g   = lane >> 2;
    const int tig = lane & 3;
    int l0 = wid * 16 + g;
    int l1 = l0 + 8;
    int li0 = l0 & 63, li1 = l1 & 63;
    float r0 = (li0 < LS) ? ((l0 >> 6) ? sn1[li0] : sn0[li0]) : 1.0f;
    float r1 = (li1 < LS) ? ((l1 >> 6) ? sn1[li1] : sn0[li1]) : 1.0f;
    float n0 = SQN ? sqrtf(r0) : r0;
    float n1 = SQN ? sqrtf(r1) : r1;
    #pragma unroll
    for (int t = 0; t < 4; ++t) {
        int q0 = t * 8 + tig * 2;
        float i0 = 1.0f / (qns[q0] * n0), i1 = 1.0f / (qns[q0 + 1] * n0);
        float i2 = 1.0f / (qns[q0] * n1), i3 = 1.0f / (qns[q0 + 1] * n1);
        if (li0 < LS) {
            simbuf[l0 * 32 + q0]     = acc[t][0] * i0;
            simbuf[l0 * 32 + q0 + 1] = acc[t][1] * i1;
        }
        if (li1 < LS) {
            simbuf[l1 * 32 + q0]     = acc[t][2] * i2;
            simbuf[l1 * 32 + q0 + 1] = acc[t][3] * i3;
        }
    }
}

__global__ void __launch_bounds__(256, 3) simpool_kernel(
    const int* __restrict__ question,
    const int* __restrict__ sentences,
    const float* __restrict__ Wg,
    const float* __restrict__ biasg,
    float* __restrict__ out_sent)
{
    extern __shared__ __align__(16) uint8_t dyn[];
    __nv_bfloat16* Qi = (__nv_bfloat16*)(dyn + OQI);
    __nv_bfloat16* Qc = (__nv_bfloat16*)(dyn + OQC);
    float* simbuf = (float*)(dyn + OSB);
    float* qns  = (float*)(dyn + OMISC);
    float* qcns = (float*)(dyn + OMISC + 128);
    float* zbuf = (float*)(dyn + OMISC + 256);
    int*   smk  = (int*)(dyn + OMISC + 512);
    int*   qmk  = (int*)(dyn + OMISC + 1024);
    float* Wc   = (float*)(dyn + OMISC + 1152);
    uint32_t sbS  = (uint32_t)__cvta_generic_to_shared(dyn + OSS);
    uint32_t sbQi = (uint32_t)__cvta_generic_to_shared(Qi);
    uint32_t sbQc = (uint32_t)__cvta_generic_to_shared(Qc);

    const int tid = threadIdx.x;
    const int b   = blockIdx.y;
    const int n0  = blockIdx.x * 2;

    constexpr int QSI = DP + 8, QSC = F + 8;
    const __nv_bfloat16* Qig = g_qe_bf + (size_t)b * LQ * DP;
    const __nv_bfloat16* Qcg = g_qc_bf + (size_t)b * LQ * F;
    for (int idx = tid; idx < 32 * (DP / 8); idx += 256) {
        int row = idx / (DP / 8), s8 = idx % (DP / 8);
        *(uint4*)&Qi[row * QSI + s8 * 8] = *(const uint4*)&Qig[(size_t)row * DP + s8 * 8];
    }
    for (int idx = tid; idx < 32 * (F / 8); idx += 256) {
        int row = idx / (F / 8), s8 = idx % (F / 8);
        *(uint4*)&Qc[row * QSC + s8 * 8] = *(const uint4*)&Qcg[(size_t)row * F + s8 * 8];
    }
    if (tid < 32) {
        qns[tid]  = g_qn[b * LQ + tid];
        qcns[tid] = sqrtf(g_qcn2[b * LQ + tid]);
        qmk[tid]  = question[b * LQ + tid] > 0;
    }
    for (int idx = tid; idx < 128; idx += 256) {
        int sent = idx >> 6, l = idx & 63;
        smk[idx] = (l < LS) ? (sentences[((size_t)b * NS + n0 + sent) * LS + l] > 0) : 0;
    }
    if (tid < 7) Wc[tid] = (tid < 6) ? Wg[tid] : biasg[0];
    __syncthreads();

    const float* sn0i = g_sn   + (size_t)b * LT + (size_t)n0 * LS;
    const float* sn1i = sn0i + LS;
    const float* sn0c = g_scn2 + (size_t)b * LT + (size_t)n0 * LS;
    const float* sn1c = sn0c + LS;
    const __nv_bfloat16* S0i = g_se_bf + ((size_t)b * LT + (size_t)n0 * LS) * DP;
    const __nv_bfloat16* S0c = g_sc_bf + ((size_t)b * LT + (size_t)n0 * LS) * F;

    const float thr = (float)(1.0 - 1e-5);

    const int grp = tid >> 2;
    const int sub = tid & 3;
    const int psent = grp >> 5, pq = grp & 31;

    // ---- phase A: sim_ins ----
    sim_phase<DP, DP, false>(sbS, sbQi, S0i, S0i + (size_t)LS * DP, simbuf, qns, sn0i, sn1i, tid);
    __syncthreads();
    {
        bool qm = qmk[pq] != 0;
        const float* col = simbuf + psent * 64 * 32 + pq;
        const int* sm = smk + psent * 64;
        float ti[5] = {-INFINITY, -INFINITY, -INFINITY, -INFINITY, -INFINITY};
        int cnt = 0;
        int lb = sub * 15;
        for (int l = lb; l < lb + 15; ++l) {
            float v = col[l * 32];
            if (v >= thr) ++cnt;
            float mv = (qm && sm[l]) ? v : 0.0f;
            insert5(ti, mv);
        }
        #pragma unroll
        for (int off = 1; off <= 2; off <<= 1) {
            cnt += __shfl_xor_sync(0xffffffffu, cnt, off);
            float ov[5];
            #pragma unroll
            for (int k = 0; k < 5; ++k) ov[k] = __shfl_xor_sync(0xffffffffu, ti[k], off);
            #pragma unroll
            for (int k = 0; k < 5; ++k) insert5(ti, ov[k]);
        }
        if (sub == 0) {
            float insMean = (ti[0] + ti[1] + ti[2] + ti[3] + ti[4]) * 0.2f;
            float ohMax   = (cnt > 0) ? 1.0f : 0.0f;
            float ohMean  = fminf((float)cnt, 5.0f) * 0.2f;
            zbuf[grp] = Wc[0] * ti[0] + Wc[1] * insMean + Wc[4] * ohMax + Wc[5] * ohMean;
        }
    }
    __syncthreads();

    // ---- phase B: sim_sen ----
    sim_phase<F, F, true>(sbS, sbQc, S0c, S0c + (size_t)LS * F, simbuf, qcns, sn0c, sn1c, tid);
    __syncthreads();
    {
        bool qm = qmk[pq] != 0;
        const float* col = simbuf + psent * 64 * 32 + pq;
        const int* sm = smk + psent * 64;
        float tc[5] = {-INFINITY, -INFINITY, -INFINITY, -INFINITY, -INFINITY};
        int lb = sub * 15;
        for (int l = lb; l < lb + 15; ++l) {
            float v = col[l * 32];
            float mv = (qm && sm[l]) ? v : 0.0f;
            insert5(tc, mv);
        }
        #pragma unroll
        for (int off = 1; off <= 2; off <<= 1) {
            float ov[5];
            #pragma unroll
            for (int k = 0; k < 5; ++k) ov[k] = __shfl_xor_sync(0xffffffffu, tc[k], off);
            #pragma unroll
            for (int k = 0; k < 5; ++k) insert5(tc, ov[k]);
        }
        if (sub == 0) {
            float senMean = (tc[0] + tc[1] + tc[2] + tc[3] + tc[4]) * 0.2f;
            float z = zbuf[grp] + Wc[2] * tc[0] + Wc[3] * senMean + Wc[6];
            zbuf[grp] = 1.0f / (1.0f + expf(-z));
        }
    }
    __syncthreads();
    if (tid < 2) {
        float s = 0.0f;
        for (int q = 0; q < 32; ++q) s += zbuf[tid * 32 + q];
        float sr = s * (1.0f / (float)LQ);
        int bn = b * NS + n0 + tid;
        g_sentrel[bn] = sr;
        if (out_sent) out_sent[bn] = sr;
    }
}

// ---------------- doc max + BCE losses ----------------
__global__ void final_kernel(const int* __restrict__ tsents,
                             const int* __restrict__ tdocs,
                             float* __restrict__ out_loss,
                             float* __restrict__ out_doc) {
    __shared__ float red[256];
    __shared__ float docs_s[Bq];
    int tid = threadIdx.x;
    const float eps = 1e-7f;
    const float hi  = (float)(1.0 - 1e-7);

    float s1 = 0.0f;
    for (int i = tid; i < Bq * NS; i += 256) {
        float p = fminf(fmaxf(g_sentrel[i], eps), hi);
        float t = (float)tsents[i];
        s1 += t * logf(p) + (1.0f - t) * log1pf(-p);
    }
    red[tid] = s1;
    __syncthreads();
    for (int s = 128; s > 0; s >>= 1) {
        if (tid < s) red[tid] += red[tid + s];
        __syncthreads();
    }
    float bce1 = -red[0] / (float)(Bq * NS);
    __syncthreads();

    if (tid < Bq) {
        float m = -INFINITY;
        for (int n = 0; n < NS; ++n) m = fmaxf(m, g_sentrel[tid * NS + n]);
        docs_s[tid] = m;
        if (out_doc) out_doc[tid] = m;
    }
    __syncthreads();

    float s2 = 0.0f;
    if (tid < Bq) {
        float p = fminf(fmaxf(docs_s[tid], eps), hi);
        float t = (float)tdocs[tid];
        s2 = t * logf(p) + (1.0f - t) * log1pf(-p);
    }
    red[tid] = s2;
    __syncthreads();
    for (int s = 128; s > 0; s >>= 1) {
        if (tid < s) red[tid] += red[tid + s];
        __syncthreads();
    }
    if (tid == 0) {
        float bce2 = -red[0] / (float)Bq;
        out_loss[0] = 0.5f * (bce1 + bce2);
    }
}

// ---------------- host ----------------
extern "C" void kernel_launch(void* const* d_in, const int* in_sizes, int n_in,
                              void* d_out, int out_size) {
    const int *sentences = nullptr, *question = nullptr, *tsents = nullptr, *tdocs = nullptr;
    const float *embeds = nullptr, *filters = nullptr, *W = nullptr, *bias = nullptr;

    for (int i = 0; i < n_in; ++i) {
        switch (in_sizes[i]) {
            case SROWS:        sentences = (const int*)d_in[i];  break;
            case QROWS:        question  = (const int*)d_in[i];  break;
            case Bq * NS:      tsents    = (const int*)d_in[i];  break;
            case Bq:           tdocs     = (const int*)d_in[i];  break;
            case Vv * D:       embeds    = (const float*)d_in[i]; break;
            case F * FS * D:   filters   = (const float*)d_in[i]; break;
            case 6:            W         = (const float*)d_in[i]; break;
            case 1:            bias      = (const float*)d_in[i]; break;
            default: break;
        }
    }

    float* out = (float*)d_out;
    float* out_sent = (out_size >= 1 + Bq * NS)      ? out + 1            : nullptr;
    float* out_doc  = (out_size >= 1 + Bq * NS + Bq) ? out + 1 + Bq * NS  : nullptr;

    cudaFuncSetAttribute(conv_mma_kernel, cudaFuncAttributeMaxDynamicSharedMemorySize, SMEM_CONV);
    cudaFuncSetAttribute(simpool_kernel, cudaFuncAttributeMaxDynamicSharedMemorySize, SMEM_SP);

    // 1: filters -> e4m3
    filt_convert_kernel<<<(F * FS * D + 255) / 256, 256>>>(filters);

    // 2: unified gather (question + sentences) + norms + cn2 zeroing
    gather_norm_kernel<<<((QROWS + SROWS) * 32 + 255) / 256, 256>>>(embeds, question, sentences);

    // 3: conv (R14 config) + row sumsq
    conv_mma_kernel<<<dim3(STILES + QTILES, F / 128), 256, SMEM_CONV>>>();

    // 4: fused sim + pool (3 CTAs/SM)
    simpool_kernel<<<dim3(NS / 2, Bq), 256, SMEM_SP>>>(question, sentences, W, bias, out_sent);

    // 5: doc max + BCE
    final_kernel<<<1, 256>>>(tsents, tdocs, out, out_doc);
}

// round 17
// speedup vs baseline: 1.2146x; 1.1500x over previous
#include <cuda_runtime.h>
#include <cuda_bf16.h>
#include <cuda_fp8.h>
#include <cstdint>
#include <math.h>

// ---------------- problem constants ----------------
constexpr int Bq   = 64;
constexpr int NS   = 50;
constexpr int LS   = 60;
constexpr int LQ   = 32;
constexpr int D    = 300;
constexpr int DP   = 320;
constexpr int F    = 256;
constexpr int FS   = 3;
constexpr int Vv   = 100000;
constexpr int QROWS = Bq * LQ;        // 2048
constexpr int SROWS = Bq * NS * LS;   // 192000
constexpr int LT    = NS * LS;        // 3000

constexpr int STK  = 64;            // K fp8 per conv stage
constexpr int STPT = DP / STK;      // 5 stages per tap
constexpr int NSTG = FS * STPT;     // 15 stages

constexpr int STILES = SROWS / 128;
constexpr int QTILES = QROWS / 128;

// conv dynamic smem: A 3x8KB @0, B 3x8KB @24576
constexpr int SMEM_CONV = 49152;

// simpool dynamic-smem (fp8 Q tiles; odd 16B-slot strides) — 53.5KB -> 4 CTAs/SM
constexpr int OQI   = 0;                 // Q ins: 32 x 336 B = 10752
constexpr int OQC   = 10752;             // Q conv: 32 x 272 B = 8704 -> 19456
constexpr int OSS   = 19456;             // S pipe: 2 x 8KB -> 35840
constexpr int OSB   = 35840;             // simbuf: 128 x 32 fp32 -> 52224
constexpr int OMISC = 52224;             // qns qcns zbuf smk qmk W
constexpr int SMEM_SP = 53504;

// ---------------- device scratch ----------------
__device__ uint8_t g_qe_f8[(QROWS + 2) * DP];   // fp8 embeds (pads stay 0)
__device__ uint8_t g_se_f8[(SROWS + 2) * DP];
__device__ uint8_t g_filt_f8[F * FS * DP];
__device__ float g_qn[QROWS];                   // norms of fp8 embed rows
__device__ float g_sn[SROWS];
__device__ uint8_t g_qc_f8[QROWS * F];          // conv outputs, fp8
__device__ uint8_t g_sc_f8[SROWS * F];
__device__ float g_qcn2[QROWS];                 // sumsq of fp8 conv rows
__device__ float g_scn2[SROWS];
__device__ float g_sentrel[Bq * NS];

// ---------------- asm helpers ----------------
__device__ __forceinline__ void mma_fp8(float* c,
                                        uint32_t a0, uint32_t a1, uint32_t a2, uint32_t a3,
                                        uint32_t b0, uint32_t b1) {
    asm volatile("mma.sync.aligned.m16n8k32.row.col.f32.e4m3.e4m3.f32 "
                 "{%0,%1,%2,%3},{%4,%5,%6,%7},{%8,%9},{%0,%1,%2,%3};"
                 : "+f"(c[0]), "+f"(c[1]), "+f"(c[2]), "+f"(c[3])
                 : "r"(a0), "r"(a1), "r"(a2), "r"(a3), "r"(b0), "r"(b1));
}
__device__ __forceinline__ void ldsm4(uint32_t& r0, uint32_t& r1, uint32_t& r2, uint32_t& r3,
                                      uint32_t addr) {
    asm volatile("ldmatrix.sync.aligned.m8n8.x4.shared.b16 {%0,%1,%2,%3}, [%4];"
                 : "=r"(r0), "=r"(r1), "=r"(r2), "=r"(r3) : "r"(addr));
}
__device__ __forceinline__ void ldsm2(uint32_t& r0, uint32_t& r1, uint32_t addr) {
    asm volatile("ldmatrix.sync.aligned.m8n8.x2.shared.b16 {%0,%1}, [%2];"
                 : "=r"(r0), "=r"(r1) : "r"(addr));
}
__device__ __forceinline__ void cp_async16(uint32_t dst, const void* src, uint32_t srcsz) {
    asm volatile("cp.async.ca.shared.global [%0], [%1], 16, %2;"
                 :: "r"(dst), "l"(src), "r"(srcsz));
}
__device__ __forceinline__ void cp_commit() { asm volatile("cp.async.commit_group;" ::: "memory"); }
__device__ __forceinline__ void cp_wait0()  { asm volatile("cp.async.wait_group 0;" ::: "memory"); }
__device__ __forceinline__ void cp_wait1()  { asm volatile("cp.async.wait_group 1;" ::: "memory"); }

// ---------------- unified gather -> fp8 + norm(from fp8); zeroes cn2 ----------------
__global__ void gather_norm_kernel(const float* __restrict__ embeds,
                                   const int* __restrict__ question,
                                   const int* __restrict__ sentences) {
    int warp = (blockIdx.x * blockDim.x + threadIdx.x) >> 5;
    int lane = threadIdx.x & 31;
    if (warp >= QROWS + SROWS) return;
    bool isq = warp < QROWS;
    int r = isq ? warp : warp - QROWS;
    int tok = isq ? question[r] : sentences[r];
    uint8_t* frow = (isq ? g_qe_f8 : g_se_f8) + (size_t)r * DP;
    float*   nrm  = (isq ? g_qn    : g_sn);
    float*   cn2  = (isq ? g_qcn2  : g_scn2);
    const float* src = embeds + (size_t)tok * D;

    float ss = 0.0f;
    #pragma unroll
    for (int it = 0; it < 3; ++it) {
        int i = lane * 4 + it * 128;
        if (i < D) {
            float4 v = *(const float4*)&src[i];
            __nv_fp8_e4m3 f0(v.x), f1(v.y), f2(v.z), f3(v.w);
            uchar4 fc;
            fc.x = *(uint8_t*)&f0; fc.y = *(uint8_t*)&f1;
            fc.z = *(uint8_t*)&f2; fc.w = *(uint8_t*)&f3;
            *(uchar4*)&frow[i] = fc;
            float x0 = float(f0), x1 = float(f1), x2 = float(f2), x3 = float(f3);
            ss += x0 * x0 + x1 * x1 + x2 * x2 + x3 * x3;
        }
    }
    #pragma unroll
    for (int o = 16; o; o >>= 1) ss += __shfl_xor_sync(0xffffffffu, ss, o);
    if (lane == 0) { nrm[r] = sqrtf(ss); cn2[r] = 0.0f; }
}

// ---------------- filter fp32 -> e4m3 ----------------
__global__ void filt_convert_kernel(const float* __restrict__ filt) {
    int idx = blockIdx.x * blockDim.x + threadIdx.x;
    if (idx >= F * FS * D) return;
    int f = idx / (FS * D);
    int r = idx % (FS * D);
    int t = r / D;
    int k = r % D;
    __nv_fp8_e4m3 f8(filt[idx]);
    g_filt_f8[((size_t)f * FS + t) * DP + k] = *(uint8_t*)&f8;
}

// ============================================================================
// conv: 128x128 CTA tile, 8 warps 4Mx2N, fp32 acc, e4m3 MMA m16n8k32,
// 3-deep cp.async pipeline, 2 CTAs/SM. Epilogue: fp8 store + row sumsq (fp8 vals).
// ============================================================================
__global__ void __launch_bounds__(256, 2) conv_mma_kernel() {
    const int bx  = blockIdx.x;
    const bool isq = (bx >= STILES);
    const uint8_t* X = isq ? g_qe_f8 : g_se_f8;
    uint8_t* out     = isq ? g_qc_f8 : g_sc_f8;
    float* cn2       = isq ? g_qcn2  : g_scn2;
    const int seg    = isq ? LQ : LS;
    const int rbase  = (isq ? (bx - STILES) : bx) * 128;

    extern __shared__ __align__(16) uint8_t sm[];
    uint32_t sb = (uint32_t)__cvta_generic_to_shared(sm);

    const int tid  = threadIdx.x;
    const int lane = tid & 31;
    const int wid  = tid >> 5;
    const int wm   = (wid & 3) * 32;
    const int wn   = (wid >> 2) * 64;
    const int m    = lane >> 3;
    const int rr   = lane & 7;

    const int fbase = blockIdx.y * 128;

    const int arow  = tid >> 1;
    const int hbase = (tid & 1) * 2;
    const int gr    = rbase + arow;
    const int lpos  = gr % seg;
    const int gf    = fbase + arow;
    const int swz   = (arow >> 1) & 3;

    float acc[2][8][4];
    #pragma unroll
    for (int i = 0; i < 2; ++i)
        #pragma unroll
        for (int j = 0; j < 8; ++j)
            #pragma unroll
            for (int v = 0; v < 4; ++v) acc[i][j][v] = 0.0f;

    auto issue = [&](int s, int buf) {
        int tap = s / STPT;
        int kc  = (s % STPT) * STK;
        uint32_t asz = ((lpos + tap) < seg) ? 16u : 0u;
        const uint8_t* ap = X + (size_t)(gr + tap) * DP + kc;
        const uint8_t* bp = g_filt_f8 + ((size_t)gf * FS + tap) * DP + kc;
        #pragma unroll
        for (int e = 0; e < 2; ++e) {
            int h = hbase + e;
            int phys = h ^ swz;
            uint32_t da = sb + buf * 8192 + arow * 64 + phys * 16;
            uint32_t db = da + 24576;
            cp_async16(da, ap + h * 16, asz);
            cp_async16(db, bp + h * 16, 16u);
        }
    };

    issue(0, 0); cp_commit();
    issue(1, 1); cp_commit();

    for (int s = 0; s < NSTG; ++s) {
        if (s + 1 < NSTG) cp_wait1(); else cp_wait0();
        __syncthreads();
        if (s + 2 < NSTG) { issue(s + 2, (s + 2) % 3); cp_commit(); }
        uint32_t abase = sb + (s % 3) * 8192;
        uint32_t bbase = abase + 24576;

        #pragma unroll
        for (int c = 0; c < 2; ++c) {
            uint32_t a[2][4];
            #pragma unroll
            for (int i = 0; i < 2; ++i) {
                int rowA = wm + i * 16 + (m & 1) * 8 + rr;
                int phys = (2 * c + (m >> 1)) ^ ((rowA >> 1) & 3);
                ldsm4(a[i][0], a[i][1], a[i][2], a[i][3],
                      abase + (uint32_t)(rowA * 64 + phys * 16));
            }
            uint32_t bbv[8][2];
            #pragma unroll
            for (int jp = 0; jp < 4; ++jp) {
                int rowB = wn + (jp * 2 + (m >> 1)) * 8 + rr;
                int phys = (2 * c + (m & 1)) ^ ((rowB >> 1) & 3);
                ldsm4(bbv[2 * jp][0], bbv[2 * jp][1], bbv[2 * jp + 1][0], bbv[2 * jp + 1][1],
                      bbase + (uint32_t)(rowB * 64 + phys * 16));
            }
            #pragma unroll
            for (int j = 0; j < 8; ++j)
                #pragma unroll
                for (int i = 0; i < 2; ++i)
                    mma_fp8(acc[i][j], a[i][0], a[i][1], a[i][2], a[i][3],
                            bbv[j][0], bbv[j][1]);
        }
        __syncthreads();
    }

    // ---- epilogue: fp8 store + per-row sumsq of the fp8-ROUNDED values ----
    const int g   = lane >> 2;
    const int tig = lane & 3;
    #pragma unroll
    for (int i = 0; i < 2; ++i) {
        int r0 = rbase + wm + i * 16 + g;
        float sq0 = 0.0f, sq8 = 0.0f;
        #pragma unroll
        for (int j = 0; j < 8; ++j) {
            int col = fbase + wn + j * 8 + tig * 2;
            __nv_fp8_e4m3 e0(acc[i][j][0]), e1(acc[i][j][1]);
            __nv_fp8_e4m3 e2(acc[i][j][2]), e3(acc[i][j][3]);
            uint8_t* o0 = out + (size_t)r0 * F + col;
            uchar2 p01; p01.x = *(uint8_t*)&e0; p01.y = *(uint8_t*)&e1;
            uchar2 p23; p23.x = *(uint8_t*)&e2; p23.y = *(uint8_t*)&e3;
            *(uchar2*)o0 = p01;
            *(uchar2*)(o0 + (size_t)8 * F) = p23;
            float f0 = float(e0), f1 = float(e1), f2 = float(e2), f3 = float(e3);
            sq0 += f0 * f0 + f1 * f1;
            sq8 += f2 * f2 + f3 * f3;
        }
        sq0 += __shfl_xor_sync(0xffffffffu, sq0, 1);
        sq0 += __shfl_xor_sync(0xffffffffu, sq0, 2);
        sq8 += __shfl_xor_sync(0xffffffffu, sq8, 1);
        sq8 += __shfl_xor_sync(0xffffffffu, sq8, 2);
        if (tig == 0) {
            atomicAdd(&cn2[r0], sq0);
            atomicAdd(&cn2[r0 + 8], sq8);
        }
    }
}

// ============================================================================
// fused sim + pool, all-fp8 operands. 2-deep S pipe, 4 CTAs/SM.
// ============================================================================
__device__ __forceinline__ void insert5(float* t, float v) {
    if (v > t[4]) {
        t[4] = v;
        #pragma unroll
        for (int i = 4; i > 0; --i) {
            if (t[i] > t[i - 1]) { float tmp = t[i - 1]; t[i - 1] = t[i]; t[i] = tmp; }
        }
    }
}

// one fp8 sim phase: KT = k bytes per row, STRIDE = global row stride (bytes)
// S streamed 64B/stage; Q resident in smem with row stride KT+16 (odd slots).
template<int KT, int STRIDE, bool SQN>
__device__ __forceinline__ void sim_phase(
    uint32_t sbS, uint32_t sbQ,
    const uint8_t* __restrict__ S0,
    const uint8_t* __restrict__ S1,
    float* __restrict__ simbuf,
    const float* __restrict__ qns,
    const float* __restrict__ sn0,
    const float* __restrict__ sn1,
    int tid)
{
    constexpr int STG  = KT / 64;      // stages (64 fp8 per stage)
    constexpr int QSTR = KT + 16;      // Q smem row stride in bytes

    const int lane = tid & 31;
    const int wid  = tid >> 5;
    const int m    = lane >> 3;
    const int rr   = lane & 7;

    const int srow  = tid >> 1;
    const int hbase = (tid & 1) * 2;
    const int sl    = srow & 63;
    const int ssent = srow >> 6;
    const int swz   = (srow >> 1) & 3;
    const uint32_t ssz = (sl < LS) ? 16u : 0u;
    const uint8_t* srcrow = (ssent ? S1 : S0) + (size_t)sl * STRIDE;

    auto issueS = [&](int s, int buf) {
        int kc = s * 64;
        #pragma unroll
        for (int e = 0; e < 2; ++e) {
            int h = hbase + e;
            int phys = h ^ swz;
            cp_async16(sbS + buf * 8192 + srow * 64 + phys * 16, srcrow + kc + h * 16, ssz);
        }
    };

    float acc[4][4];
    #pragma unroll
    for (int t = 0; t < 4; ++t)
        #pragma unroll
        for (int v = 0; v < 4; ++v) acc[t][v] = 0.0f;

    issueS(0, 0); cp_commit();

    for (int s = 0; s < STG; ++s) {
        cp_wait0();
        __syncthreads();
        if (s + 1 < STG) { issueS(s + 1, (s + 1) & 1); cp_commit(); }
        uint32_t abase = sbS + (s & 1) * 8192;

        #pragma unroll
        for (int c = 0; c < 2; ++c) {           // two 32B k-chunks per stage
            uint32_t a[4];
            int rowS = wid * 16 + (m & 1) * 8 + rr;
            int phys = (2 * c + (m >> 1)) ^ ((rowS >> 1) & 3);
            ldsm4(a[0], a[1], a[2], a[3], abase + (uint32_t)(rowS * 64 + phys * 16));

            int cg = s * 2 + c;
            uint32_t qb[4][2];
            #pragma unroll
            for (int jp = 0; jp < 2; ++jp) {
                int rowq = (jp * 2 + (m >> 1)) * 8 + rr;
                uint32_t qaddr = sbQ + (uint32_t)(rowq * QSTR + cg * 32 + (m & 1) * 16);
                ldsm4(qb[2 * jp][0], qb[2 * jp][1], qb[2 * jp + 1][0], qb[2 * jp + 1][1], qaddr);
            }
            #pragma unroll
            for (int t = 0; t < 4; ++t)
                mma_fp8(acc[t], a[0], a[1], a[2], a[3], qb[t][0], qb[t][1]);
        }
        __syncthreads();
    }

    const int g   = lane >> 2;
    const int tig = lane & 3;
    int l0 = wid * 16 + g;
    int l1 = l0 + 8;
    int li0 = l0 & 63, li1 = l1 & 63;
    float r0 = (li0 < LS) ? ((l0 >> 6) ? sn1[li0] : sn0[li0]) : 1.0f;
    float r1 = (li1 < LS) ? ((l1 >> 6) ? sn1[li1] : sn0[li1]) : 1.0f;
    float n0 = SQN ? sqrtf(r0) : r0;
    float n1 = SQN ? sqrtf(r1) : r1;
    #pragma unroll
    for (int t = 0; t < 4; ++t) {
        int q0 = t * 8 + tig * 2;
        float i0 = 1.0f / (qns[q0] * n0), i1 = 1.0f / (qns[q0 + 1] * n0);
        float i2 = 1.0f / (qns[q0] * n1), i3 = 1.0f / (qns[q0 + 1] * n1);
        if (li0 < LS) {
            simbuf[l0 * 32 + q0]     = acc[t][0] * i0;
            simbuf[l0 * 32 + q0 + 1] = acc[t][1] * i1;
        }
        if (li1 < LS) {
            simbuf[l1 * 32 + q0]     = acc[t][2] * i2;
            simbuf[l1 * 32 + q0 + 1] = acc[t][3] * i3;
        }
    }
}

__global__ void __launch_bounds__(256, 4) simpool_kernel(
    const int* __restrict__ question,
    const int* __restrict__ sentences,
    const float* __restrict__ Wg,
    const float* __restrict__ biasg,
    float* __restrict__ out_sent)
{
    extern __shared__ __align__(16) uint8_t dyn[];
    uint8_t* Qi = dyn + OQI;     // 32 x (DP+16) fp8
    uint8_t* Qc = dyn + OQC;     // 32 x (F+16) fp8
    float* simbuf = (float*)(dyn + OSB);
    float* qns  = (float*)(dyn + OMISC);
    float* qcns = (float*)(dyn + OMISC + 128);
    float* zbuf = (float*)(dyn + OMISC + 256);
    int*   smk  = (int*)(dyn + OMISC + 512);
    int*   qmk  = (int*)(dyn + OMISC + 1024);
    float* Wc   = (float*)(dyn + OMISC + 1152);
    uint32_t sbS  = (uint32_t)__cvta_generic_to_shared(dyn + OSS);
    uint32_t sbQi = (uint32_t)__cvta_generic_to_shared(Qi);
    uint32_t sbQc = (uint32_t)__cvta_generic_to_shared(Qc);

    const int tid = threadIdx.x;
    const int b   = blockIdx.y;
    const int n0  = blockIdx.x * 2;

    const uint8_t* Qig = g_qe_f8 + (size_t)b * LQ * DP;
    const uint8_t* Qcg = g_qc_f8 + (size_t)b * LQ * F;
    for (int idx = tid; idx < 32 * (DP / 16); idx += 256) {
        int row = idx / (DP / 16), s16 = idx % (DP / 16);
        *(uint4*)&Qi[row * (DP + 16) + s16 * 16] = *(const uint4*)&Qig[(size_t)row * DP + s16 * 16];
    }
    for (int idx = tid; idx < 32 * (F / 16); idx += 256) {
        int row = idx / (F / 16), s16 = idx % (F / 16);
        *(uint4*)&Qc[row * (F + 16) + s16 * 16] = *(const uint4*)&Qcg[(size_t)row * F + s16 * 16];
    }
    if (tid < 32) {
        qns[tid]  = g_qn[b * LQ + tid];
        qcns[tid] = sqrtf(g_qcn2[b * LQ + tid]);
        qmk[tid]  = question[b * LQ + tid] > 0;
    }
    for (int idx = tid; idx < 128; idx += 256) {
        int sent = idx >> 6, l = idx & 63;
        smk[idx] = (l < LS) ? (sentences[((size_t)b * NS + n0 + sent) * LS + l] > 0) : 0;
    }
    if (tid < 7) Wc[tid] = (tid < 6) ? Wg[tid] : biasg[0];
    __syncthreads();

    const float* sn0i = g_sn   + (size_t)b * LT + (size_t)n0 * LS;
    const float* sn1i = sn0i + LS;
    const float* sn0c = g_scn2 + (size_t)b * LT + (size_t)n0 * LS;
    const float* sn1c = sn0c + LS;
    const uint8_t* S0i = g_se_f8 + ((size_t)b * LT + (size_t)n0 * LS) * DP;
    const uint8_t* S0c = g_sc_f8 + ((size_t)b * LT + (size_t)n0 * LS) * F;

    const float thr = (float)(1.0 - 1e-5);

    const int grp = tid >> 2;
    const int sub = tid & 3;
    const int psent = grp >> 5, pq = grp & 31;

    // ---- phase A: sim_ins (fp8) ----
    sim_phase<DP, DP, false>(sbS, sbQi, S0i, S0i + (size_t)LS * DP, simbuf, qns, sn0i, sn1i, tid);
    __syncthreads();
    {
        bool qm = qmk[pq] != 0;
        const float* col = simbuf + psent * 64 * 32 + pq;
        const int* sm = smk + psent * 64;
        float ti[5] = {-INFINITY, -INFINITY, -INFINITY, -INFINITY, -INFINITY};
        int cnt = 0;
        int lb = sub * 15;
        for (int l = lb; l < lb + 15; ++l) {
            float v = col[l * 32];
            if (v >= thr) ++cnt;
            float mv = (qm && sm[l]) ? v : 0.0f;
            insert5(ti, mv);
        }
        #pragma unroll
        for (int off = 1; off <= 2; off <<= 1) {
            cnt += __shfl_xor_sync(0xffffffffu, cnt, off);
            float ov[5];
            #pragma unroll
            for (int k = 0; k < 5; ++k) ov[k] = __shfl_xor_sync(0xffffffffu, ti[k], off);
            #pragma unroll
            for (int k = 0; k < 5; ++k) insert5(ti, ov[k]);
        }
        if (sub == 0) {
            float insMean = (ti[0] + ti[1] + ti[2] + ti[3] + ti[4]) * 0.2f;
            float ohMax   = (cnt > 0) ? 1.0f : 0.0f;
            float ohMean  = fminf((float)cnt, 5.0f) * 0.2f;
            zbuf[grp] = Wc[0] * ti[0] + Wc[1] * insMean + Wc[4] * ohMax + Wc[5] * ohMean;
        }
    }
    __syncthreads();

    // ---- phase B: sim_sen (fp8) ----
    sim_phase<F, F, true>(sbS, sbQc, S0c, S0c + (size_t)LS * F, simbuf, qcns, sn0c, sn1c, tid);
    __syncthreads();
    {
        bool qm = qmk[pq] != 0;
        const float* col = simbuf + psent * 64 * 32 + pq;
        const int* sm = smk + psent * 64;
        float tc[5] = {-INFINITY, -INFINITY, -INFINITY, -INFINITY, -INFINITY};
        int lb = sub * 15;
        for (int l = lb; l < lb + 15; ++l) {
            float v = col[l * 32];
            float mv = (qm && sm[l]) ? v : 0.0f;
            insert5(tc, mv);
        }
        #pragma unroll
        for (int off = 1; off <= 2; off <<= 1) {
            float ov[5];
            #pragma unroll
            for (int k = 0; k < 5; ++k) ov[k] = __shfl_xor_sync(0xffffffffu, tc[k], off);
            #pragma unroll
            for (int k = 0; k < 5; ++k) insert5(tc, ov[k]);
        }
        if (sub == 0) {
            float senMean = (tc[0] + tc[1] + tc[2] + tc[3] + tc[4]) * 0.2f;
            float z = zbuf[grp] + Wc[2] * tc[0] + Wc[3] * senMean + Wc[6];
            zbuf[grp] = 1.0f / (1.0f + expf(-z));
        }
    }
    __syncthreads();
    if (tid < 2) {
        float s = 0.0f;
        for (int q = 0; q < 32; ++q) s += zbuf[tid * 32 + q];
        float sr = s * (1.0f / (float)LQ);
        int bn = b * NS + n0 + tid;
        g_sentrel[bn] = sr;
        if (out_sent) out_sent[bn] = sr;
    }
}

// ---------------- doc max + BCE losses ----------------
__global__ void final_kernel(const int* __restrict__ tsents,
                             const int* __restrict__ tdocs,
                             float* __restrict__ out_loss,
                             float* __restrict__ out_doc) {
    __shared__ float red[256];
    __shared__ float docs_s[Bq];
    int tid = threadIdx.x;
    const float eps = 1e-7f;
    const float hi  = (float)(1.0 - 1e-7);

    float s1 = 0.0f;
    for (int i = tid; i < Bq * NS; i += 256) {
        float p = fminf(fmaxf(g_sentrel[i], eps), hi);
        float t = (float)tsents[i];
        s1 += t * logf(p) + (1.0f - t) * log1pf(-p);
    }
    red[tid] = s1;
    __syncthreads();
    for (int s = 128; s > 0; s >>= 1) {
        if (tid < s) red[tid] += red[tid + s];
        __syncthreads();
    }
    float bce1 = -red[0] / (float)(Bq * NS);
    __syncthreads();

    if (tid < Bq) {
        float m = -INFINITY;
        for (int n = 0; n < NS; ++n) m = fmaxf(m, g_sentrel[tid * NS + n]);
        docs_s[tid] = m;
        if (out_doc) out_doc[tid] = m;
    }
    __syncthreads();

    float s2 = 0.0f;
    if (tid < Bq) {
        float p = fminf(fmaxf(docs_s[tid], eps), hi);
        float t = (float)tdocs[tid];
        s2 = t * logf(p) + (1.0f - t) * log1pf(-p);
    }
    red[tid] = s2;
    __syncthreads();
    for (int s = 128; s > 0; s >>= 1) {
        if (tid < s) red[tid] += red[tid + s];
        __syncthreads();
    }
    if (tid == 0) {
        float bce2 = -red[0] / (float)Bq;
        out_loss[0] = 0.5f * (bce1 + bce2);
    }
}

// ---------------- host ----------------
extern "C" void kernel_launch(void* const* d_in, const int* in_sizes, int n_in,
                              void* d_out, int out_size) {
    const int *sentences = nullptr, *question = nullptr, *tsents = nullptr, *tdocs = nullptr;
    const float *embeds = nullptr, *filters = nullptr, *W = nullptr, *bias = nullptr;

    for (int i = 0; i < n_in; ++i) {
        switch (in_sizes[i]) {
            case SROWS:        sentences = (const int*)d_in[i];  break;
            case QROWS:        question  = (const int*)d_in[i];  break;
            case Bq * NS:      tsents    = (const int*)d_in[i];  break;
            case Bq:           tdocs     = (const int*)d_in[i];  break;
            case Vv * D:       embeds    = (const float*)d_in[i]; break;
            case F * FS * D:   filters   = (const float*)d_in[i]; break;
            case 6:            W         = (const float*)d_in[i]; break;
            case 1:            bias      = (const float*)d_in[i]; break;
            default: break;
        }
    }

    float* out = (float*)d_out;
    float* out_sent = (out_size >= 1 + Bq * NS)      ? out + 1            : nullptr;
    float* out_doc  = (out_size >= 1 + Bq * NS + Bq) ? out + 1 + Bq * NS  : nullptr;

    cudaFuncSetAttribute(conv_mma_kernel, cudaFuncAttributeMaxDynamicSharedMemorySize, SMEM_CONV);
    cudaFuncSetAttribute(simpool_kernel, cudaFuncAttributeMaxDynamicSharedMemorySize, SMEM_SP);

    // 1: filters -> e4m3
    filt_convert_kernel<<<(F * FS * D + 255) / 256, 256>>>(filters);

    // 2: unified gather -> fp8 + norms + cn2 zeroing
    gather_norm_kernel<<<((QROWS + SROWS) * 32 + 255) / 256, 256>>>(embeds, question, sentences);

    // 3: conv (fp8 in, fp8 out) + row sumsq
    conv_mma_kernel<<<dim3(STILES + QTILES, F / 128), 256, SMEM_CONV>>>();

    // 4: fused sim + pool (all-fp8 operands, 4 CTAs/SM)
    simpool_kernel<<<dim3(NS / 2, Bq), 256, SMEM_SP>>>(question, sentences, W, bias, out_sent);

    // 5: doc max + BCE
    final_kernel<<<1, 256>>>(tsents, tdocs, out, out_doc);
}